// round 11
// baseline (speedup 1.0000x reference)
#include <cuda_runtime.h>

// ---------------------------------------------------------------------------
// TexturedSoftPhongShader — R7: 2 pixels/thread for doubled MLP
//  - R6's corner-parallel prep (unchanged, proven)
//  - shade: thread t handles pixels {blk*512+t, blk*512+256+t}; all six
//    wave-1 loads batched up front; per-k active paths of both pixels
//    interleaved so their gathers overlap.
// Inputs (metadata order):
//  0 texels (N,H,W,K,3) f32 | 1 bary (N,H,W,K,3) f32 | 2 zbuf (N,H,W,K) f32
//  3 dists (N,H,W,K) f32 | 4 verts (unused) | 5 vertex_normals (V,3) f32
//  6 gamma (N,27) f32 | 7 pix_to_face (N,H,W,K) i32 | 8 faces (F,3) i32
// Output: (N,H,W,4) f32
// ---------------------------------------------------------------------------

#define MAXF 70000

// 64B per face record (3 corners + pad): record never straddles a 128B line.
__device__ float4 g_fn[MAXF * 4];

__global__ __launch_bounds__(256)
void prep_kernel(const int* __restrict__ faces,
                 const float* __restrict__ vn, int FC) {
    int idx = blockIdx.x * blockDim.x + threadIdx.x;   // 0 .. 3F-1
    if (idx >= FC) return;
    int f      = idx / 3;
    int corner = idx - 3 * f;
    int v      = faces[idx];
    const float* nr = vn + 3 * v;
    g_fn[4 * f + corner] = make_float4(nr[0], nr[1], nr[2], 0.f);
}

// Per-sample active-path body: gather + SH lighting + weighted accumulate.
__device__ __forceinline__ void sample_body(
    int face, float w, const float* __restrict__ bp,
    const float* __restrict__ tp, int k, const float (*sC)[3],
    float& accR, float& accG, float& accB)
{
    float b0 = bp[3 * k + 0], b1 = bp[3 * k + 1], b2 = bp[3 * k + 2];
    const float4* fp = g_fn + 4 * face;
    float4 v0 = fp[0];
    float4 v1 = fp[1];
    float4 v2 = fp[2];
    float mx = b0 * v0.x + b1 * v1.x + b2 * v2.x;
    float my = b0 * v0.y + b1 * v1.y + b2 * v2.y;
    float mz = b0 * v0.z + b1 * v1.z + b2 * v2.z;

    float pxy = mx * my;
    float pyz = my * mz;
    float pxz = mx * mz;
    float pzz = mz * mz;
    float pd  = fmaf(-my, my, mx * mx);

    float Lr = sC[0][0] + sC[1][0]*my + sC[2][0]*mz + sC[3][0]*mx
             + sC[4][0]*pxy + sC[5][0]*pyz + sC[6][0]*pzz
             + sC[7][0]*pxz + sC[8][0]*pd;
    float Lg = sC[0][1] + sC[1][1]*my + sC[2][1]*mz + sC[3][1]*mx
             + sC[4][1]*pxy + sC[5][1]*pyz + sC[6][1]*pzz
             + sC[7][1]*pxz + sC[8][1]*pd;
    float Lb = sC[0][2] + sC[1][2]*my + sC[2][2]*mz + sC[3][2]*mx
             + sC[4][2]*pxy + sC[5][2]*pyz + sC[6][2]*pzz
             + sC[7][2]*pxz + sC[8][2]*pd;

    accR = fmaf(w, Lr * tp[3 * k + 0], accR);
    accG = fmaf(w, Lg * tp[3 * k + 1], accG);
    accB = fmaf(w, Lb * tp[3 * k + 2], accB);
}

__global__ __launch_bounds__(256, 3)
void shade_kernel(const float*  __restrict__ texels,
                  const float*  __restrict__ bary,
                  const float4* __restrict__ zbuf4,
                  const float4* __restrict__ dists4,
                  const int4*   __restrict__ p2f4,
                  const float*  __restrict__ gamma,
                  float4*       __restrict__ out,
                  int HW, int P) {
    const float A0C0   = 0.8862269254527580f;
    const float A1C1   = 1.7724538509055159f;
    const float A2C2   = 2.4270323670f;
    const float A2C2D0 = 0.7006239630f;

    const float EPS       = 1e-10f;
    const float INV_SIGMA = 1e4f;
    const float INV_GAMMA = 1e4f;
    const float INV_ZR    = 1.0f / 99.0f;

    __shared__ float sC[9][3];
    int tid  = threadIdx.x;
    int pix0 = blockIdx.x * 512;          // block covers 512 pixels
    if (tid < 3) {
        int c = tid;
        int n0 = pix0 / HW;               // whole block in one image (HW%512==0)
        const float* gp = gamma + n0 * 27 + c * 9;
        float g0 = gp[0] + 0.8f;
        float g6 = gp[6];
        sC[0][c] = A0C0 * g0 - A2C2D0 * g6;
        sC[1][c] = A1C1 * gp[1];
        sC[2][c] = A1C1 * gp[2];
        sC[3][c] = A1C1 * gp[3];
        sC[4][c] = A2C2 * gp[4];
        sC[5][c] = A2C2 * gp[5];
        sC[6][c] = 3.0f * A2C2D0 * g6;
        sC[7][c] = A2C2 * gp[7];
        sC[8][c] = A2C2 * 0.5f * gp[8];
    }
    __syncthreads();

    int pixA = pix0 + tid;
    int pixB = pixA + 256;
    if (pixB >= P) pixB = pixA;           // safe tail (grid sized exactly anyway)

    // ---- Wave 1: six independent 128-bit loads, front-batched (MLP ~6)
    float4 zA = zbuf4[pixA];
    float4 dA = dists4[pixA];
    int4   fA = p2f4[pixA];
    float4 zB = zbuf4[pixB];
    float4 dB = dists4[pixB];
    int4   fB = p2f4[pixB];

    float zvA[4] = {zA.x, zA.y, zA.z, zA.w};
    float dvA[4] = {dA.x, dA.y, dA.z, dA.w};
    int   fvA[4] = {fA.x, fA.y, fA.z, fA.w};
    float zvB[4] = {zB.x, zB.y, zB.z, zB.w};
    float dvB[4] = {dB.x, dB.y, dB.z, dB.w};
    int   fvB[4] = {fB.x, fB.y, fB.z, fB.w};

    float ziA[4], ziB[4];
    float zmaxA = EPS, zmaxB = EPS;
#pragma unroll
    for (int k = 0; k < 4; k++) {
        ziA[k] = (fvA[k] >= 0) ? (100.0f - zvA[k]) * INV_ZR : 0.0f;
        zmaxA  = fmaxf(zmaxA, ziA[k]);
        ziB[k] = (fvB[k] >= 0) ? (100.0f - zvB[k]) * INV_ZR : 0.0f;
        zmaxB  = fmaxf(zmaxB, ziB[k]);
    }

    const float* tpA = texels + (size_t)pixA * 12;
    const float* bpA = bary   + (size_t)pixA * 12;
    const float* tpB = texels + (size_t)pixB * 12;
    const float* bpB = bary   + (size_t)pixB * 12;

    float accRA = 0.f, accGA = 0.f, accBA = 0.f, wsumA = 0.f, omaA = 1.f;
    float accRB = 0.f, accGB = 0.f, accBB = 0.f, wsumB = 0.f, omaB = 1.f;

    // ---- Pass 2: interleave A.k and B.k so active-path gathers overlap.
    // Heavy path only where exp doesn't underflow (exact 0 in reference too).
#pragma unroll
    for (int k = 0; k < 4; k++) {
        if (fvA[k] >= 0) {
            float prob = __fdividef(1.0f, 1.0f + __expf(dvA[k] * INV_SIGMA));
            omaA *= (1.0f - prob);
            float arg = (ziA[k] - zmaxA) * INV_GAMMA;
            if (arg > -87.0f) {
                float w = prob * __expf(arg);
                wsumA += w;
                sample_body(fvA[k], w, bpA, tpA, k, sC, accRA, accGA, accBA);
            }
        }
        if (fvB[k] >= 0) {
            float prob = __fdividef(1.0f, 1.0f + __expf(dvB[k] * INV_SIGMA));
            omaB *= (1.0f - prob);
            float arg = (ziB[k] - zmaxB) * INV_GAMMA;
            if (arg > -87.0f) {
                float w = prob * __expf(arg);
                wsumB += w;
                sample_body(fvB[k], w, bpB, tpB, k, sC, accRB, accGB, accBB);
            }
        }
    }

    float deltaA  = fmaxf(__expf((EPS - zmaxA) * INV_GAMMA), EPS);
    float invdenA = __fdividef(1.0f, wsumA + deltaA);
    float bgA     = deltaA * invdenA;
    float deltaB  = fmaxf(__expf((EPS - zmaxB) * INV_GAMMA), EPS);
    float invdenB = __fdividef(1.0f, wsumB + deltaB);
    float bgB     = deltaB * invdenB;

    float4 oA, oB;
    oA.x = fmaf(accRA, invdenA, bgA);
    oA.y = fmaf(accGA, invdenA, bgA);
    oA.z = fmaf(accBA, invdenA, bgA);
    oA.w = 1.0f - omaA;
    oB.x = fmaf(accRB, invdenB, bgB);
    oB.y = fmaf(accGB, invdenB, bgB);
    oB.z = fmaf(accBB, invdenB, bgB);
    oB.w = 1.0f - omaB;

    if (pixA < P) out[pixA] = oA;
    if (pixB != pixA) out[pixB] = oB;
}

extern "C" void kernel_launch(void* const* d_in, const int* in_sizes, int n_in,
                              void* d_out, int out_size) {
    const float* texels = (const float*)d_in[0];
    const float* bary   = (const float*)d_in[1];
    const float* zbuf   = (const float*)d_in[2];
    const float* dists  = (const float*)d_in[3];
    const float* vn     = (const float*)d_in[5];
    const float* gamma  = (const float*)d_in[6];
    const int*   p2f    = (const int*)d_in[7];
    const int*   faces  = (const int*)d_in[8];

    int FC = in_sizes[8];            // 3*F corners
    if (FC > MAXF * 3) FC = MAXF * 3;
    int P = in_sizes[2] / 4;
    int N = in_sizes[6] / 27;
    int HW = P / N;

    prep_kernel<<<(FC + 255) / 256, 256>>>(faces, vn, FC);
    shade_kernel<<<(P + 511) / 512, 256>>>(
        texels, bary,
        (const float4*)zbuf, (const float4*)dists,
        (const int4*)p2f, gamma, (float4*)d_out, HW, P);
}